// round 3
// baseline (speedup 1.0000x reference)
#include <cuda_runtime.h>

#define BB   32
#define CINN 16
#define COUTT 32
#define HH   14
#define WW   14
#define KK   5
#define OHH  5
#define OWW  5
#define HWSZ (HH*WW)        // 196
#define IMG  (HWSZ*HWSZ)    // 38416
#define IMG4 (IMG/4)        // 9604

// Scratch (global device arrays; no allocations)
__device__ float g_Csum[BB * IMG];                               // ~4.9 MB
__device__ float g_T[(size_t)BB * COUTT * OHH * OWW * HWSZ];     // ~20 MB

// ---------------------------------------------------------------------------
// Kernel 1: Csum[b, h2,w2, h4,w4] = sum_c C[b,c,...]   (streams 78.7 MB)
// ---------------------------------------------------------------------------
__global__ void reduce_c_kernel(const float4* __restrict__ C4) {
    int idx = blockIdx.x * blockDim.x + threadIdx.x;
    if (idx >= BB * IMG4) return;
    int b = idx / IMG4;
    int j = idx - b * IMG4;
    const float4* p = C4 + (size_t)b * CINN * IMG4 + j;
    float ax = 0.f, ay = 0.f, az = 0.f, aw = 0.f;
#pragma unroll
    for (int c = 0; c < CINN; c++) {
        float4 v = p[(size_t)c * IMG4];
        ax += v.x; ay += v.y; az += v.z; aw += v.w;
    }
    reinterpret_cast<float4*>(g_Csum)[idx] = make_float4(ax, ay, az, aw);
}

// ---------------------------------------------------------------------------
// Kernel 2: first conv (over dims 4,5) for ALL 32 output channels at once.
// T[b][i][y1*5+x1][h2*14+w2] = sum_k w[i,k] * Csum[b, h2,w2, win(y1,x1)]
// grid = (25, B), block = 224 threads (tid<196 = one (h2,w2) each)
// ---------------------------------------------------------------------------
__global__ void conv1_kernel(const float* __restrict__ w) {
    __shared__ float ws[COUTT * 25];
    int tid = threadIdx.x;
    for (int k = tid; k < COUTT * 25; k += blockDim.x) ws[k] = w[k];
    __syncthreads();

    int yx = blockIdx.x;          // 0..24
    int b  = blockIdx.y;
    int y1 = yx / OWW, x1 = yx % OWW;

    if (tid < HWSZ) {
        const float* src = g_Csum + (size_t)b * IMG + (size_t)tid * HWSZ
                           + (2 * y1) * WW + 2 * x1;
        float patch[25];
#pragma unroll
        for (int r = 0; r < KK; r++)
#pragma unroll
            for (int c = 0; c < KK; c++)
                patch[r * KK + c] = __ldg(src + r * WW + c);

        float* dst = g_T + (((size_t)b * COUTT) * 25 + yx) * HWSZ + tid;
#pragma unroll 4
        for (int i = 0; i < COUTT; i++) {
            float acc = 0.f;
#pragma unroll
            for (int k = 0; k < 25; k++) acc += patch[k] * ws[i * 25 + k];
            dst[(size_t)i * 25 * HWSZ] = acc;   // coalesced across tid
        }
    }
}

// ---------------------------------------------------------------------------
// Kernel 3: second conv (over dims 2,3).
// out_cov[b,i,y2,x2,y1,x1] = sum_a w[i,a] * T[b,i,y1x1, win(y2,x2)]
// grid = B*COUT blocks, block = 640 threads (tid<625 = one output each)
// ---------------------------------------------------------------------------
__global__ void conv2_kernel(const float* __restrict__ w,
                             float* __restrict__ out_cov) {
    __shared__ float Ts[25 * HWSZ];   // 4900 floats = 19.6 KB
    __shared__ float ws[25];
    int tid = threadIdx.x;
    int bi  = blockIdx.x;             // b*32 + i
    int i   = bi % COUTT;

    const float* tsrc = g_T + (size_t)bi * 25 * HWSZ;
    for (int k = tid; k < 25 * HWSZ; k += blockDim.x) Ts[k] = tsrc[k];
    if (tid < 25) ws[tid] = w[i * 25 + tid];
    __syncthreads();

    if (tid < 625) {
        int q = tid / 25;             // y2*5+x2
        int p = tid - q * 25;         // y1*5+x1
        int y2 = q / OWW, x2 = q % OWW;
        const float* base = Ts + p * HWSZ + (2 * y2) * WW + 2 * x2;
        float acc = 0.f;
#pragma unroll
        for (int r = 0; r < KK; r++)
#pragma unroll
            for (int c = 0; c < KK; c++)
                acc += ws[r * KK + c] * base[r * WW + c];
        out_cov[(size_t)bi * 625 + tid] = acc;   // coalesced
    }
}

// ---------------------------------------------------------------------------
// Kernel 4: mean path.  out_mean[b,i,y,x] = sum_c conv(u[b,c], w[i])
// ---------------------------------------------------------------------------
__global__ void mean_kernel(const float* __restrict__ u,
                            const float* __restrict__ w,
                            float* __restrict__ out) {
    int idx = blockIdx.x * blockDim.x + threadIdx.x;
    if (idx >= BB * COUTT * OHH * OWW) return;
    int x = idx % OWW;
    int y = (idx / OWW) % OHH;
    int i = (idx / (OHH * OWW)) % COUTT;
    int b = idx / (COUTT * OHH * OWW);

    float wk[25];
#pragma unroll
    for (int k = 0; k < 25; k++) wk[k] = w[i * 25 + k];

    float acc = 0.f;
    for (int c = 0; c < CINN; c++) {
        const float* up = u + ((size_t)(b * CINN + c) * HH + 2 * y) * WW + 2 * x;
#pragma unroll
        for (int r = 0; r < KK; r++)
#pragma unroll
            for (int q = 0; q < KK; q++)
                acc += up[r * WW + q] * wk[r * KK + q];
    }
    out[idx] = acc;
}

// ---------------------------------------------------------------------------
extern "C" void kernel_launch(void* const* d_in, const int* in_sizes, int n_in,
                              void* d_out, int out_size) {
    const float* u = (const float*)d_in[0];   // [32,16,14,14]
    const float* C = (const float*)d_in[1];   // [32,16,14,14,14,14]
    const float* w = (const float*)d_in[2];   // [32,1,5,5]
    float* out      = (float*)d_out;
    float* out_mean = out;                               // 25600 floats
    float* out_cov  = out + BB * COUTT * OHH * OWW;      // 640000 floats

    // 1) channel reduction of C (HBM-bound, ~78.7 MB read)
    reduce_c_kernel<<<(BB * IMG4 + 255) / 256, 256>>>((const float4*)C);

    // 2) first conv over dims (4,5), shared across all 32 kernels
    dim3 g1(OHH * OWW, BB);
    conv1_kernel<<<g1, 224>>>(w);

    // 3) second conv over dims (2,3)
    conv2_kernel<<<BB * COUTT, 640>>>(w, out_cov);

    // 4) mean path (independent of the above)
    mean_kernel<<<(BB * COUTT * OHH * OWW + 255) / 256, 256>>>(u, w, out_mean);
}